// round 7
// baseline (speedup 1.0000x reference)
#include <cuda_runtime.h>
#include <cuda_fp16.h>

#define NN 100000
#define EE 1600000
#define TE (EE + NN)
#define NB_SCAN ((NN + 1023) / 1024)
#define SX2_STRIDE 136

// ---------------- scratch (static device globals; no allocation) -----------
__device__ __align__(16) __half g_h1[NN * 128];    // layer1 linear output (fp16)
__device__ __align__(16) __half g_h2[NN * 32];     // layer2 linear output (fp16)
__device__ __align__(16) float g_asrc1[NN * 4];
__device__ __align__(16) float g_adst1[NN * 4];
__device__ __align__(16) float g_asrc2[NN];
__device__ __align__(16) float g_adst2[NN];
__device__ int   g_deg[NN];
__device__ int   g_rowstart[NN + 1];
__device__ int   g_cursor[NN];
__device__ int   g_csr[TE];
__device__ int   g_blockval[NB_SCAN];
__device__ int   g_blockflag[NB_SCAN];
__device__ int   g_is32;          // 1 if edge_index is int32, 0 if int64

__device__ __forceinline__ float lrelu(float x) { return x > 0.f ? x : 0.2f * x; }

// packed f32x2 helpers (sm_100+)
__device__ __forceinline__ unsigned long long pack2(float a, float b) {
    unsigned long long r;
    asm("mov.b64 %0, {%1, %2};" : "=l"(r) : "f"(a), "f"(b));
    return r;
}
__device__ __forceinline__ void unpack2(unsigned long long p, float& a, float& b) {
    asm("mov.b64 {%0, %1}, %2;" : "=f"(a), "=f"(b) : "l"(p));
}
__device__ __forceinline__ void ffma2(unsigned long long& acc, unsigned long long a,
                                      unsigned long long b) {
    asm("fma.rn.f32x2 %0, %1, %2, %0;" : "+l"(acc) : "l"(a), "l"(b));
}

// ---------------- init + edge dtype detection ------------------------------
__global__ void k_init(const void* __restrict__ ei) {
    int i = blockIdx.x * blockDim.x + threadIdx.x;
    if (i < NN) { g_deg[i] = 1; g_cursor[i] = 0; }   // deg starts at 1 = self loop
    if (i < NB_SCAN) g_blockflag[i] = 0;
    if (i == 0) {
        const long long* p = (const long long*)ei;
        int bad = 0;
        for (int j = 0; j < 64; j++) {
            long long v = p[j];
            if (v < 0 || v >= NN) bad = 1;
        }
        g_is32 = bad;   // int32 data read as int64 -> garbage out of range
    }
}

__device__ __forceinline__ int load_src(const void* ei, int e) {
    return g_is32 ? ((const int*)ei)[e] : (int)((const long long*)ei)[e];
}
__device__ __forceinline__ int load_dst(const void* ei, int e) {
    return g_is32 ? ((const int*)ei)[EE + e] : (int)((const long long*)ei)[EE + e];
}

// ---------------- CSR build -----------------------------------------------
__global__ void k_count(const void* __restrict__ ei) {
    int e = blockIdx.x * blockDim.x + threadIdx.x;
    if (e < EE) {
        int d = load_dst(ei, e);
        if ((unsigned)d < NN) atomicAdd(&g_deg[d], 1);
    }
}

// single-kernel scan: block-local scan + publish aggregate + lookback sum
__global__ void k_scan(void) {
    __shared__ int sh[1024];
    __shared__ int s_excl;
    int t = threadIdx.x;
    int b = blockIdx.x;
    int i = b * 1024 + t;
    int v = (i < NN) ? g_deg[i] : 0;
    sh[t] = v;
    __syncthreads();
    #pragma unroll
    for (int off = 1; off < 1024; off <<= 1) {
        int a = (t >= off) ? sh[t - off] : 0;
        __syncthreads();
        sh[t] += a;
        __syncthreads();
    }
    if (t == 1023) {
        g_blockval[b] = sh[1023];
        __threadfence();
        atomicExch(&g_blockflag[b], 1);
    }
    if (t < 32) {
        int excl = 0;
        for (int w0 = b - 1; w0 >= 0; w0 -= 32) {
            int idx = w0 - t;
            int val = 0;
            if (idx >= 0) {
                while (atomicAdd(&g_blockflag[idx], 0) == 0) {}
                __threadfence();
                val = g_blockval[idx];
            }
            #pragma unroll
            for (int off = 16; off; off >>= 1)
                val += __shfl_xor_sync(0xffffffffu, val, off);
            excl += val;
        }
        if (t == 0) s_excl = excl;
    }
    __syncthreads();
    if (i < NN) g_rowstart[i + 1] = sh[t] + s_excl;
    if (i == 0) g_rowstart[0] = 0;
}

__global__ void k_fill(const void* __restrict__ ei) {
    int t = blockIdx.x * blockDim.x + threadIdx.x;
    if (t >= TE) return;
    int s, d;
    if (t < EE) {
        s = load_src(ei, t);
        d = load_dst(ei, t);
    } else {
        s = d = t - EE;   // self loop
    }
    if ((unsigned)s >= NN || (unsigned)d >= NN) return;
    int pos = g_rowstart[d] + atomicAdd(&g_cursor[d], 1);
    if ((unsigned)pos < TE) g_csr[pos] = s;
}

// ---------------- GEMM1: h1 = x @ W1 (128x128) + fused attention coeffs ----
__global__ void k_gemm1(const float* __restrict__ x, const float* __restrict__ W1,
                        const float* __restrict__ att_src, const float* __restrict__ att_dst) {
    extern __shared__ float sm[];
    float* sW = sm;                // 128*128
    float* sX = sm + 128 * 128;    // 64*128
    int tid = threadIdx.x;
    int row0 = blockIdx.x * 64;

    float4* sW4 = (float4*)sW;
    const float4* W4 = (const float4*)W1;
    for (int j = tid; j < 4096; j += 256) sW4[j] = W4[j];

    float4* sX4 = (float4*)sX;
    const float4* X4 = (const float4*)x;
    for (int j = tid; j < 2048; j += 256) {
        int r = j >> 5, c = j & 31;
        int gr = row0 + r;
        sX4[j] = (gr < NN) ? X4[gr * 32 + c] : make_float4(0.f, 0.f, 0.f, 0.f);
    }
    __syncthreads();

    int tc = tid & 31;
    int tr = tid >> 5;
    unsigned long long accp[8][2];
    #pragma unroll
    for (int r = 0; r < 8; r++) { accp[r][0] = 0ull; accp[r][1] = 0ull; }

    for (int k4 = 0; k4 < 32; k4++) {
        float4 xq[8];
        #pragma unroll
        for (int r = 0; r < 8; r++) xq[r] = sX4[(tr * 8 + r) * 32 + k4];
        #pragma unroll
        for (int kk = 0; kk < 4; kk++) {
            float4 w = sW4[(k4 * 4 + kk) * 32 + tc];
            unsigned long long wlo = pack2(w.x, w.y);
            unsigned long long whi = pack2(w.z, w.w);
            #pragma unroll
            for (int r = 0; r < 8; r++) {
                float xv = (kk == 0) ? xq[r].x : (kk == 1) ? xq[r].y
                          : (kk == 2) ? xq[r].z : xq[r].w;
                unsigned long long xp = pack2(xv, xv);
                ffma2(accp[r][0], xp, wlo);
                ffma2(accp[r][1], xp, whi);
            }
        }
    }

    float4 av_s = ((const float4*)att_src)[tc];
    float4 av_d = ((const float4*)att_dst)[tc];
    int head = tc >> 3;

    uint2* H2 = (uint2*)g_h1;
    #pragma unroll
    for (int r = 0; r < 8; r++) {
        float4 h;
        unpack2(accp[r][0], h.x, h.y);
        unpack2(accp[r][1], h.z, h.w);
        int gr = row0 + tr * 8 + r;
        if (gr < NN) {
            __half2 p01 = __floats2half2_rn(h.x, h.y);
            __half2 p23 = __floats2half2_rn(h.z, h.w);
            uint2 v;
            v.x = *(unsigned*)&p01;
            v.y = *(unsigned*)&p23;
            H2[gr * 32 + tc] = v;
        }

        float s = h.x * av_s.x + h.y * av_s.y + h.z * av_s.z + h.w * av_s.w;
        float d = h.x * av_d.x + h.y * av_d.y + h.z * av_d.z + h.w * av_d.w;
        #pragma unroll
        for (int off = 4; off; off >>= 1) {
            s += __shfl_xor_sync(0xffffffffu, s, off);
            d += __shfl_xor_sync(0xffffffffu, d, off);
        }
        if ((tc & 7) == 0 && gr < NN) {
            g_asrc1[gr * 4 + head] = s;
            g_adst1[gr * 4 + head] = d;
        }
    }
}

// ---------------- fused: agg1 (128-node tile -> smem) + GEMM2 + att2 -------
// block 256 thr; Phase A: 8 warps x 16 nodes aggregation into smem tile;
// Phase B: gemm2 on smem tile + fused layer-2 attention coefficients.
__global__ void k_agg1_gemm2(const float* __restrict__ b1, const float* __restrict__ W2,
                             const float* __restrict__ att_src, const float* __restrict__ att_dst) {
    extern __shared__ float sm[];
    float* sW = sm;                 // 128*32
    float* sX = sm + 128 * 32;      // 128*136 (padded) — agg1 output tile
    int tid = threadIdx.x;
    int warp = tid >> 5, lane = tid & 31;
    int row0 = blockIdx.x * 128;

    // load W2 tile
    float4* sW4 = (float4*)sW;
    const float4* W4 = (const float4*)W2;
    for (int j = tid; j < 1024; j += 256) sW4[j] = W4[j];

    // ---- Phase A: aggregation for 16 nodes per warp ----
    int head = lane >> 3;
    float4 b = ((const float4*)b1)[lane];
    const uint2* H2g = (const uint2*)g_h1;
    const float4* A4 = (const float4*)g_asrc1;

    for (int j = 0; j < 16; j++) {
        int n = row0 + warp * 16 + j;
        int loc = warp * 16 + j;
        if (n >= NN) {
            *(float4*)&sX[loc * SX2_STRIDE + lane * 4] = make_float4(0.f, 0.f, 0.f, 0.f);
            continue;
        }
        int base = g_rowstart[n];
        int K = g_rowstart[n + 1] - base;
        float4 ad = ((const float4*)g_adst1)[n];
        float ad_s = head < 2 ? (head == 0 ? ad.x : ad.y) : (head == 2 ? ad.z : ad.w);

        float den = 0.f;
        float4 acc = make_float4(0.f, 0.f, 0.f, 0.f);
        const int* csr = g_csr + base;

        int i = 0;
        for (; i + 3 < K; i += 4) {
            int s0 = csr[i], s1 = csr[i + 1], s2 = csr[i + 2], s3 = csr[i + 3];
            float4 as0 = A4[s0], as1 = A4[s1], as2 = A4[s2], as3 = A4[s3];
            uint2 v0 = H2g[s0 * 32 + lane];
            uint2 v1 = H2g[s1 * 32 + lane];
            uint2 v2 = H2g[s2 * 32 + lane];
            uint2 v3 = H2g[s3 * 32 + lane];
            float a0 = head < 2 ? (head == 0 ? as0.x : as0.y) : (head == 2 ? as0.z : as0.w);
            float a1 = head < 2 ? (head == 0 ? as1.x : as1.y) : (head == 2 ? as1.z : as1.w);
            float a2 = head < 2 ? (head == 0 ? as2.x : as2.y) : (head == 2 ? as2.z : as2.w);
            float a3 = head < 2 ? (head == 0 ? as3.x : as3.y) : (head == 2 ? as3.z : as3.w);
            float e0 = __expf(lrelu(a0 + ad_s));
            float e1 = __expf(lrelu(a1 + ad_s));
            float e2 = __expf(lrelu(a2 + ad_s));
            float e3 = __expf(lrelu(a3 + ad_s));
            den += (e0 + e1) + (e2 + e3);
            float2 f0a = __half22float2(*(__half2*)&v0.x);
            float2 f0b = __half22float2(*(__half2*)&v0.y);
            float2 f1a = __half22float2(*(__half2*)&v1.x);
            float2 f1b = __half22float2(*(__half2*)&v1.y);
            float2 f2a = __half22float2(*(__half2*)&v2.x);
            float2 f2b = __half22float2(*(__half2*)&v2.y);
            float2 f3a = __half22float2(*(__half2*)&v3.x);
            float2 f3b = __half22float2(*(__half2*)&v3.y);
            acc.x += (e0 * f0a.x + e1 * f1a.x) + (e2 * f2a.x + e3 * f3a.x);
            acc.y += (e0 * f0a.y + e1 * f1a.y) + (e2 * f2a.y + e3 * f3a.y);
            acc.z += (e0 * f0b.x + e1 * f1b.x) + (e2 * f2b.x + e3 * f3b.x);
            acc.w += (e0 * f0b.y + e1 * f1b.y) + (e2 * f2b.y + e3 * f3b.y);
        }
        for (; i < K; i++) {
            int s0 = csr[i];
            float4 as0 = A4[s0];
            uint2 v0 = H2g[s0 * 32 + lane];
            float a0 = head < 2 ? (head == 0 ? as0.x : as0.y) : (head == 2 ? as0.z : as0.w);
            float e0 = __expf(lrelu(a0 + ad_s));
            den += e0;
            float2 f0a = __half22float2(*(__half2*)&v0.x);
            float2 f0b = __half22float2(*(__half2*)&v0.y);
            acc.x += e0 * f0a.x;
            acc.y += e0 * f0a.y;
            acc.z += e0 * f0b.x;
            acc.w += e0 * f0b.y;
        }

        float inv = 1.f / (den + 1e-16f);
        float4 o;
        o.x = fmaxf(acc.x * inv + b.x, 0.f);
        o.y = fmaxf(acc.y * inv + b.y, 0.f);
        o.z = fmaxf(acc.z * inv + b.z, 0.f);
        o.w = fmaxf(acc.w * inv + b.w, 0.f);
        *(float4*)&sX[loc * SX2_STRIDE + lane * 4] = o;
    }
    __syncthreads();

    // ---- Phase B: gemm2 on smem tile + fused att2 ----
    int tc = tid & 7;     // cols 4*tc..4*tc+3
    int tr = tid >> 3;    // rows tr, tr+32, tr+64, tr+96
    unsigned long long accp[4][2];
    #pragma unroll
    for (int m = 0; m < 4; m++) { accp[m][0] = 0ull; accp[m][1] = 0ull; }

    for (int k4 = 0; k4 < 32; k4++) {
        float4 xq[4];
        #pragma unroll
        for (int m = 0; m < 4; m++)
            xq[m] = *(const float4*)&sX[(tr + 32 * m) * SX2_STRIDE + k4 * 4];
        #pragma unroll
        for (int kk = 0; kk < 4; kk++) {
            float4 w = sW4[(k4 * 4 + kk) * 8 + tc];
            unsigned long long wlo = pack2(w.x, w.y);
            unsigned long long whi = pack2(w.z, w.w);
            #pragma unroll
            for (int m = 0; m < 4; m++) {
                float xv = (kk == 0) ? xq[m].x : (kk == 1) ? xq[m].y
                          : (kk == 2) ? xq[m].z : xq[m].w;
                unsigned long long xp = pack2(xv, xv);
                ffma2(accp[m][0], xp, wlo);
                ffma2(accp[m][1], xp, whi);
            }
        }
    }

    float4 av_s = ((const float4*)att_src)[tc];
    float4 av_d = ((const float4*)att_dst)[tc];

    uint2* H2 = (uint2*)g_h2;
    #pragma unroll
    for (int m = 0; m < 4; m++) {
        float4 h;
        unpack2(accp[m][0], h.x, h.y);
        unpack2(accp[m][1], h.z, h.w);
        int gr = row0 + tr + 32 * m;
        if (gr < NN) {
            __half2 p01 = __floats2half2_rn(h.x, h.y);
            __half2 p23 = __floats2half2_rn(h.z, h.w);
            uint2 v;
            v.x = *(unsigned*)&p01;
            v.y = *(unsigned*)&p23;
            H2[gr * 8 + tc] = v;
        }

        float s = h.x * av_s.x + h.y * av_s.y + h.z * av_s.z + h.w * av_s.w;
        float d = h.x * av_d.x + h.y * av_d.y + h.z * av_d.z + h.w * av_d.w;
        #pragma unroll
        for (int off = 4; off; off >>= 1) {
            s += __shfl_xor_sync(0xffffffffu, s, off);
            d += __shfl_xor_sync(0xffffffffu, d, off);
        }
        if (tc == 0 && gr < NN) {
            g_asrc2[gr] = s;
            g_adst2[gr] = d;
        }
    }
}

// ---------------- aggregation, layer 2 (1 head x 32 ch, fp16, unroll 4) ----
__global__ void k_agg2(const float* __restrict__ b2, float* __restrict__ out) {
    int warp = threadIdx.x >> 5, lane = threadIdx.x & 31;
    int n = blockIdx.x * 8 + warp;
    if (n >= NN) return;
    int base = g_rowstart[n];
    int K = g_rowstart[n + 1] - base;
    float ad = g_adst2[n];
    const int* csr = g_csr + base;

    float den = 0.f, acc = 0.f;
    int i = 0;
    for (; i + 3 < K; i += 4) {
        int s0 = csr[i], s1 = csr[i + 1], s2 = csr[i + 2], s3 = csr[i + 3];
        float a0 = g_asrc2[s0];
        float a1 = g_asrc2[s1];
        float a2 = g_asrc2[s2];
        float a3 = g_asrc2[s3];
        float h0 = __half2float(g_h2[s0 * 32 + lane]);
        float h1 = __half2float(g_h2[s1 * 32 + lane]);
        float h2 = __half2float(g_h2[s2 * 32 + lane]);
        float h3 = __half2float(g_h2[s3 * 32 + lane]);
        float e0 = __expf(lrelu(a0 + ad));
        float e1 = __expf(lrelu(a1 + ad));
        float e2 = __expf(lrelu(a2 + ad));
        float e3 = __expf(lrelu(a3 + ad));
        den += (e0 + e1) + (e2 + e3);
        acc += (e0 * h0 + e1 * h1) + (e2 * h2 + e3 * h3);
    }
    for (; i < K; i++) {
        int s0 = csr[i];
        float e0 = __expf(lrelu(g_asrc2[s0] + ad));
        den += e0;
        acc += e0 * __half2float(g_h2[s0 * 32 + lane]);
    }
    out[n * 32 + lane] = acc / (den + 1e-16f) + b2[lane];
}

// ---------------- launch ---------------------------------------------------
extern "C" void kernel_launch(void* const* d_in, const int* in_sizes, int n_in,
                              void* d_out, int out_size) {
    const float* x        = (const float*)d_in[0];
    const void*  ei       = d_in[1];
    const float* W1       = (const float*)d_in[2];
    const float* att_src1 = (const float*)d_in[3];
    const float* att_dst1 = (const float*)d_in[4];
    const float* b1       = (const float*)d_in[5];
    const float* W2       = (const float*)d_in[6];
    const float* att_src2 = (const float*)d_in[7];
    const float* att_dst2 = (const float*)d_in[8];
    const float* b2       = (const float*)d_in[9];
    float*       out      = (float*)d_out;

    const int SMEM_G1 = (128 * 128 + 64 * 128) * 4;
    const int SMEM_F  = (128 * 32 + 128 * SX2_STRIDE) * 4;
    cudaFuncSetAttribute(k_gemm1, cudaFuncAttributeMaxDynamicSharedMemorySize, SMEM_G1);
    cudaFuncSetAttribute(k_agg1_gemm2, cudaFuncAttributeMaxDynamicSharedMemorySize, SMEM_F);

    // side stream + events for fork/join (leaked: host-side only, ~2 calls total)
    cudaStream_t s1;
    cudaStreamCreateWithFlags(&s1, cudaStreamNonBlocking);
    cudaEvent_t evA, evB;
    cudaEventCreateWithFlags(&evA, cudaEventDisableTiming);
    cudaEventCreateWithFlags(&evB, cudaEventDisableTiming);

    // init (both branches depend on it)
    k_init<<<(NN + 255) / 256, 256>>>(ei);
    cudaEventRecord(evA, 0);
    cudaStreamWaitEvent(s1, evA, 0);

    // side stream: CSR build
    k_count<<<(EE + 255) / 256, 256, 0, s1>>>(ei);
    k_scan<<<NB_SCAN, 1024, 0, s1>>>();
    k_fill<<<(TE + 255) / 256, 256, 0, s1>>>(ei);
    cudaEventRecord(evB, s1);

    // main stream: GEMM1 (independent of CSR) runs concurrently
    k_gemm1<<<(NN + 63) / 64, 256, SMEM_G1>>>(x, W1, att_src1, att_dst1);

    // join, then fused agg1+gemm2+att2
    cudaStreamWaitEvent(0, evB, 0);
    k_agg1_gemm2<<<(NN + 127) / 128, 256, SMEM_F>>>(b1, W2, att_src2, att_dst2);

    // layer 2 aggregation
    k_agg2<<<(NN + 7) / 8, 256>>>(b2, out);
}

// round 8
// speedup vs baseline: 1.1464x; 1.1464x over previous
#include <cuda_runtime.h>
#include <cuda_fp16.h>

#define NN 100000
#define EE 1600000
#define TE (EE + NN)
#define NB_SCAN ((NN + 1023) / 1024)
#define SX2_STRIDE 136

// ---------------- scratch (static device globals; no allocation) -----------
__device__ __align__(16) __half g_h1[NN * 128];    // layer1 linear output (fp16)
__device__ __align__(16) float  g_out1[NN * 128];  // relu(layer1 agg out)
__device__ __align__(16) __half g_h2[NN * 32];     // layer2 linear output (fp16)
__device__ __align__(16) float g_asrc1[NN * 4];
__device__ __align__(16) float g_adst1[NN * 4];
__device__ __align__(16) float g_asrc2[NN];
__device__ __align__(16) float g_adst2[NN];
__device__ int   g_deg[NN];
__device__ int   g_rowstart[NN + 1];
__device__ int   g_cursor[NN];
__device__ int   g_csr[TE];
__device__ int   g_blockval[NB_SCAN];
__device__ int   g_blockflag[NB_SCAN];
__device__ int   g_is32;          // 1 if edge_index is int32, 0 if int64

__device__ __forceinline__ float lrelu(float x) { return x > 0.f ? x : 0.2f * x; }

// packed f32x2 helpers (sm_100+)
__device__ __forceinline__ unsigned long long pack2(float a, float b) {
    unsigned long long r;
    asm("mov.b64 %0, {%1, %2};" : "=l"(r) : "f"(a), "f"(b));
    return r;
}
__device__ __forceinline__ void unpack2(unsigned long long p, float& a, float& b) {
    asm("mov.b64 {%0, %1}, %2;" : "=f"(a), "=f"(b) : "l"(p));
}
__device__ __forceinline__ void ffma2(unsigned long long& acc, unsigned long long a,
                                      unsigned long long b) {
    asm("fma.rn.f32x2 %0, %1, %2, %0;" : "+l"(acc) : "l"(a), "l"(b));
}

// ---------------- init + edge dtype detection ------------------------------
__global__ void k_init(const void* __restrict__ ei) {
    int i = blockIdx.x * blockDim.x + threadIdx.x;
    if (i < NN) { g_deg[i] = 1; g_cursor[i] = 0; }   // deg starts at 1 = self loop
    if (i < NB_SCAN) g_blockflag[i] = 0;
    if (i == 0) {
        const long long* p = (const long long*)ei;
        int bad = 0;
        for (int j = 0; j < 64; j++) {
            long long v = p[j];
            if (v < 0 || v >= NN) bad = 1;
        }
        g_is32 = bad;   // int32 data read as int64 -> garbage out of range
    }
}

__device__ __forceinline__ int load_src(const void* ei, int e) {
    return g_is32 ? ((const int*)ei)[e] : (int)((const long long*)ei)[e];
}
__device__ __forceinline__ int load_dst(const void* ei, int e) {
    return g_is32 ? ((const int*)ei)[EE + e] : (int)((const long long*)ei)[EE + e];
}

// ---------------- CSR build -----------------------------------------------
__global__ void k_count(const void* __restrict__ ei) {
    int e = blockIdx.x * blockDim.x + threadIdx.x;
    if (e < EE) {
        int d = load_dst(ei, e);
        if ((unsigned)d < NN) atomicAdd(&g_deg[d], 1);
    }
}

// single-kernel scan: block-local scan + publish aggregate + lookback sum
__global__ void k_scan(void) {
    __shared__ int sh[1024];
    __shared__ int s_excl;
    int t = threadIdx.x;
    int b = blockIdx.x;
    int i = b * 1024 + t;
    int v = (i < NN) ? g_deg[i] : 0;
    sh[t] = v;
    __syncthreads();
    #pragma unroll
    for (int off = 1; off < 1024; off <<= 1) {
        int a = (t >= off) ? sh[t - off] : 0;
        __syncthreads();
        sh[t] += a;
        __syncthreads();
    }
    if (t == 1023) {
        g_blockval[b] = sh[1023];
        __threadfence();
        atomicExch(&g_blockflag[b], 1);
    }
    if (t < 32) {
        int excl = 0;
        for (int w0 = b - 1; w0 >= 0; w0 -= 32) {
            int idx = w0 - t;
            int val = 0;
            if (idx >= 0) {
                while (atomicAdd(&g_blockflag[idx], 0) == 0) {}
                __threadfence();
                val = g_blockval[idx];
            }
            #pragma unroll
            for (int off = 16; off; off >>= 1)
                val += __shfl_xor_sync(0xffffffffu, val, off);
            excl += val;
        }
        if (t == 0) s_excl = excl;
    }
    __syncthreads();
    if (i < NN) g_rowstart[i + 1] = sh[t] + s_excl;
    if (i == 0) g_rowstart[0] = 0;
}

__global__ void k_fill(const void* __restrict__ ei) {
    int t = blockIdx.x * blockDim.x + threadIdx.x;
    if (t >= TE) return;
    int s, d;
    if (t < EE) {
        s = load_src(ei, t);
        d = load_dst(ei, t);
    } else {
        s = d = t - EE;   // self loop
    }
    if ((unsigned)s >= NN || (unsigned)d >= NN) return;
    int pos = g_rowstart[d] + atomicAdd(&g_cursor[d], 1);
    if ((unsigned)pos < TE) g_csr[pos] = s;
}

// ---------------- GEMM1: h1 = x @ W1 (128x128) + fused attention coeffs ----
__global__ void k_gemm1(const float* __restrict__ x, const float* __restrict__ W1,
                        const float* __restrict__ att_src, const float* __restrict__ att_dst) {
    extern __shared__ float sm[];
    float* sW = sm;                // 128*128
    float* sX = sm + 128 * 128;    // 64*128
    int tid = threadIdx.x;
    int row0 = blockIdx.x * 64;

    float4* sW4 = (float4*)sW;
    const float4* W4 = (const float4*)W1;
    for (int j = tid; j < 4096; j += 256) sW4[j] = W4[j];

    float4* sX4 = (float4*)sX;
    const float4* X4 = (const float4*)x;
    for (int j = tid; j < 2048; j += 256) {
        int r = j >> 5, c = j & 31;
        int gr = row0 + r;
        sX4[j] = (gr < NN) ? X4[gr * 32 + c] : make_float4(0.f, 0.f, 0.f, 0.f);
    }
    __syncthreads();

    int tc = tid & 31;
    int tr = tid >> 5;
    unsigned long long accp[8][2];
    #pragma unroll
    for (int r = 0; r < 8; r++) { accp[r][0] = 0ull; accp[r][1] = 0ull; }

    for (int k4 = 0; k4 < 32; k4++) {
        float4 xq[8];
        #pragma unroll
        for (int r = 0; r < 8; r++) xq[r] = sX4[(tr * 8 + r) * 32 + k4];
        #pragma unroll
        for (int kk = 0; kk < 4; kk++) {
            float4 w = sW4[(k4 * 4 + kk) * 32 + tc];
            unsigned long long wlo = pack2(w.x, w.y);
            unsigned long long whi = pack2(w.z, w.w);
            #pragma unroll
            for (int r = 0; r < 8; r++) {
                float xv = (kk == 0) ? xq[r].x : (kk == 1) ? xq[r].y
                          : (kk == 2) ? xq[r].z : xq[r].w;
                unsigned long long xp = pack2(xv, xv);
                ffma2(accp[r][0], xp, wlo);
                ffma2(accp[r][1], xp, whi);
            }
        }
    }

    float4 av_s = ((const float4*)att_src)[tc];
    float4 av_d = ((const float4*)att_dst)[tc];
    int head = tc >> 3;

    uint2* H2 = (uint2*)g_h1;
    #pragma unroll
    for (int r = 0; r < 8; r++) {
        float4 h;
        unpack2(accp[r][0], h.x, h.y);
        unpack2(accp[r][1], h.z, h.w);
        int gr = row0 + tr * 8 + r;
        if (gr < NN) {
            __half2 p01 = __floats2half2_rn(h.x, h.y);
            __half2 p23 = __floats2half2_rn(h.z, h.w);
            uint2 v;
            v.x = *(unsigned*)&p01;
            v.y = *(unsigned*)&p23;
            H2[gr * 32 + tc] = v;
        }

        float s = h.x * av_s.x + h.y * av_s.y + h.z * av_s.z + h.w * av_s.w;
        float d = h.x * av_d.x + h.y * av_d.y + h.z * av_d.z + h.w * av_d.w;
        #pragma unroll
        for (int off = 4; off; off >>= 1) {
            s += __shfl_xor_sync(0xffffffffu, s, off);
            d += __shfl_xor_sync(0xffffffffu, d, off);
        }
        if ((tc & 7) == 0 && gr < NN) {
            g_asrc1[gr * 4 + head] = s;
            g_adst1[gr * 4 + head] = d;
        }
    }
}

// ---------------- aggregation, layer 1 (scalar attention gathers) ----------
__global__ void k_agg1(const float* __restrict__ b1) {
    int warp = threadIdx.x >> 5, lane = threadIdx.x & 31;
    int n = blockIdx.x * 16 + warp;
    if (n >= NN) return;
    int base = g_rowstart[n];
    int K = g_rowstart[n + 1] - base;

    int head = lane >> 3;
    float ad_s = g_adst1[n * 4 + head];

    float den = 0.f;
    float4 acc = make_float4(0.f, 0.f, 0.f, 0.f);
    const uint2* H2 = (const uint2*)g_h1;
    const float* AS = g_asrc1;
    const int* csr = g_csr + base;

    int i = 0;
    for (; i + 3 < K; i += 4) {
        int s0 = csr[i], s1 = csr[i + 1], s2 = csr[i + 2], s3 = csr[i + 3];
        float a0 = AS[s0 * 4 + head];
        float a1 = AS[s1 * 4 + head];
        float a2 = AS[s2 * 4 + head];
        float a3 = AS[s3 * 4 + head];
        uint2 v0 = H2[s0 * 32 + lane];
        uint2 v1 = H2[s1 * 32 + lane];
        uint2 v2 = H2[s2 * 32 + lane];
        uint2 v3 = H2[s3 * 32 + lane];
        float e0 = __expf(lrelu(a0 + ad_s));
        float e1 = __expf(lrelu(a1 + ad_s));
        float e2 = __expf(lrelu(a2 + ad_s));
        float e3 = __expf(lrelu(a3 + ad_s));
        den += (e0 + e1) + (e2 + e3);
        float2 f0a = __half22float2(*(__half2*)&v0.x);
        float2 f0b = __half22float2(*(__half2*)&v0.y);
        float2 f1a = __half22float2(*(__half2*)&v1.x);
        float2 f1b = __half22float2(*(__half2*)&v1.y);
        float2 f2a = __half22float2(*(__half2*)&v2.x);
        float2 f2b = __half22float2(*(__half2*)&v2.y);
        float2 f3a = __half22float2(*(__half2*)&v3.x);
        float2 f3b = __half22float2(*(__half2*)&v3.y);
        acc.x += (e0 * f0a.x + e1 * f1a.x) + (e2 * f2a.x + e3 * f3a.x);
        acc.y += (e0 * f0a.y + e1 * f1a.y) + (e2 * f2a.y + e3 * f3a.y);
        acc.z += (e0 * f0b.x + e1 * f1b.x) + (e2 * f2b.x + e3 * f3b.x);
        acc.w += (e0 * f0b.y + e1 * f1b.y) + (e2 * f2b.y + e3 * f3b.y);
    }
    for (; i < K; i++) {
        int s0 = csr[i];
        float a0 = AS[s0 * 4 + head];
        uint2 v0 = H2[s0 * 32 + lane];
        float e0 = __expf(lrelu(a0 + ad_s));
        den += e0;
        float2 f0a = __half22float2(*(__half2*)&v0.x);
        float2 f0b = __half22float2(*(__half2*)&v0.y);
        acc.x += e0 * f0a.x;
        acc.y += e0 * f0a.y;
        acc.z += e0 * f0b.x;
        acc.w += e0 * f0b.y;
    }

    float inv = 1.f / (den + 1e-16f);
    float4 b = ((const float4*)b1)[lane];
    float4 o;
    o.x = fmaxf(acc.x * inv + b.x, 0.f);
    o.y = fmaxf(acc.y * inv + b.y, 0.f);
    o.z = fmaxf(acc.z * inv + b.z, 0.f);
    o.w = fmaxf(acc.w * inv + b.w, 0.f);
    ((float4*)g_out1)[n * 32 + lane] = o;
}

// ---------------- GEMM2: h2 = out1 @ W2 (128x32) + fused attention coeffs --
__global__ void k_gemm2(const float* __restrict__ W2,
                        const float* __restrict__ att_src, const float* __restrict__ att_dst) {
    extern __shared__ float sm[];
    float* sW = sm;                 // 128*32
    float* sX = sm + 128 * 32;      // 128*136 (padded)
    int tid = threadIdx.x;
    int row0 = blockIdx.x * 128;

    float4* sW4 = (float4*)sW;
    const float4* W4 = (const float4*)W2;
    for (int j = tid; j < 1024; j += 256) sW4[j] = W4[j];

    const float4* X4 = (const float4*)g_out1;
    for (int j = tid; j < 4096; j += 256) {
        int r = j >> 5, c = j & 31;
        int gr = row0 + r;
        float4 v = (gr < NN) ? X4[gr * 32 + c] : make_float4(0.f, 0.f, 0.f, 0.f);
        *(float4*)&sX[r * SX2_STRIDE + c * 4] = v;
    }
    __syncthreads();

    int tc = tid & 7;
    int tr = tid >> 3;
    unsigned long long accp[4][2];
    #pragma unroll
    for (int m = 0; m < 4; m++) { accp[m][0] = 0ull; accp[m][1] = 0ull; }

    for (int k4 = 0; k4 < 32; k4++) {
        float4 xq[4];
        #pragma unroll
        for (int m = 0; m < 4; m++)
            xq[m] = *(const float4*)&sX[(tr + 32 * m) * SX2_STRIDE + k4 * 4];
        #pragma unroll
        for (int kk = 0; kk < 4; kk++) {
            float4 w = sW4[(k4 * 4 + kk) * 8 + tc];
            unsigned long long wlo = pack2(w.x, w.y);
            unsigned long long whi = pack2(w.z, w.w);
            #pragma unroll
            for (int m = 0; m < 4; m++) {
                float xv = (kk == 0) ? xq[m].x : (kk == 1) ? xq[m].y
                          : (kk == 2) ? xq[m].z : xq[m].w;
                unsigned long long xp = pack2(xv, xv);
                ffma2(accp[m][0], xp, wlo);
                ffma2(accp[m][1], xp, whi);
            }
        }
    }

    float4 av_s = ((const float4*)att_src)[tc];
    float4 av_d = ((const float4*)att_dst)[tc];

    uint2* H2 = (uint2*)g_h2;
    #pragma unroll
    for (int m = 0; m < 4; m++) {
        float4 h;
        unpack2(accp[m][0], h.x, h.y);
        unpack2(accp[m][1], h.z, h.w);
        int gr = row0 + tr + 32 * m;
        if (gr < NN) {
            __half2 p01 = __floats2half2_rn(h.x, h.y);
            __half2 p23 = __floats2half2_rn(h.z, h.w);
            uint2 v;
            v.x = *(unsigned*)&p01;
            v.y = *(unsigned*)&p23;
            H2[gr * 8 + tc] = v;
        }

        float s = h.x * av_s.x + h.y * av_s.y + h.z * av_s.z + h.w * av_s.w;
        float d = h.x * av_d.x + h.y * av_d.y + h.z * av_d.z + h.w * av_d.w;
        #pragma unroll
        for (int off = 4; off; off >>= 1) {
            s += __shfl_xor_sync(0xffffffffu, s, off);
            d += __shfl_xor_sync(0xffffffffu, d, off);
        }
        if (tc == 0 && gr < NN) {
            g_asrc2[gr] = s;
            g_adst2[gr] = d;
        }
    }
}

// ---------------- aggregation, layer 2 ------------------------------------
__global__ void k_agg2(const float* __restrict__ b2, float* __restrict__ out) {
    int warp = threadIdx.x >> 5, lane = threadIdx.x & 31;
    int n = blockIdx.x * 16 + warp;
    if (n >= NN) return;
    int base = g_rowstart[n];
    int K = g_rowstart[n + 1] - base;
    float ad = g_adst2[n];
    const int* csr = g_csr + base;

    float den = 0.f, acc = 0.f;
    int i = 0;
    for (; i + 3 < K; i += 4) {
        int s0 = csr[i], s1 = csr[i + 1], s2 = csr[i + 2], s3 = csr[i + 3];
        float a0 = g_asrc2[s0];
        float a1 = g_asrc2[s1];
        float a2 = g_asrc2[s2];
        float a3 = g_asrc2[s3];
        float h0 = __half2float(g_h2[s0 * 32 + lane]);
        float h1 = __half2float(g_h2[s1 * 32 + lane]);
        float h2 = __half2float(g_h2[s2 * 32 + lane]);
        float h3 = __half2float(g_h2[s3 * 32 + lane]);
        float e0 = __expf(lrelu(a0 + ad));
        float e1 = __expf(lrelu(a1 + ad));
        float e2 = __expf(lrelu(a2 + ad));
        float e3 = __expf(lrelu(a3 + ad));
        den += (e0 + e1) + (e2 + e3);
        acc += (e0 * h0 + e1 * h1) + (e2 * h2 + e3 * h3);
    }
    for (; i < K; i++) {
        int s0 = csr[i];
        float e0 = __expf(lrelu(g_asrc2[s0] + ad));
        den += e0;
        acc += e0 * __half2float(g_h2[s0 * 32 + lane]);
    }
    out[n * 32 + lane] = acc / (den + 1e-16f) + b2[lane];
}

// ---------------- launch ---------------------------------------------------
extern "C" void kernel_launch(void* const* d_in, const int* in_sizes, int n_in,
                              void* d_out, int out_size) {
    const float* x        = (const float*)d_in[0];
    const void*  ei       = d_in[1];
    const float* W1       = (const float*)d_in[2];
    const float* att_src1 = (const float*)d_in[3];
    const float* att_dst1 = (const float*)d_in[4];
    const float* b1       = (const float*)d_in[5];
    const float* W2       = (const float*)d_in[6];
    const float* att_src2 = (const float*)d_in[7];
    const float* att_dst2 = (const float*)d_in[8];
    const float* b2       = (const float*)d_in[9];
    float*       out      = (float*)d_out;

    const int SMEM_G1 = (128 * 128 + 64 * 128) * 4;
    const int SMEM_G2 = (128 * 32 + 128 * SX2_STRIDE) * 4;
    cudaFuncSetAttribute(k_gemm1, cudaFuncAttributeMaxDynamicSharedMemorySize, SMEM_G1);
    cudaFuncSetAttribute(k_gemm2, cudaFuncAttributeMaxDynamicSharedMemorySize, SMEM_G2);

    // side stream + events for fork/join (host-side resources only)
    cudaStream_t s1;
    cudaStreamCreateWithFlags(&s1, cudaStreamNonBlocking);
    cudaEvent_t evA, evB;
    cudaEventCreateWithFlags(&evA, cudaEventDisableTiming);
    cudaEventCreateWithFlags(&evB, cudaEventDisableTiming);

    // init (both branches depend on it)
    k_init<<<(NN + 255) / 256, 256>>>(ei);                              // launch #1
    cudaEventRecord(evA, 0);
    cudaStreamWaitEvent(s1, evA, 0);

    // side stream: CSR build (count, scan submitted before gemm1; fill after —
    // submission order chosen so k_gemm1 is the 4th launch for ncu capture)
    k_count<<<(EE + 255) / 256, 256, 0, s1>>>(ei);                      // #2
    k_scan<<<NB_SCAN, 1024, 0, s1>>>();                                 // #3

    // main stream: GEMM1 (independent of CSR) runs concurrently
    k_gemm1<<<(NN + 63) / 64, 256, SMEM_G1>>>(x, W1, att_src1, att_dst1); // #4 (ncu target)

    k_fill<<<(TE + 255) / 256, 256, 0, s1>>>(ei);                       // #5
    cudaEventRecord(evB, s1);

    // join: aggregation needs both CSR and h1
    cudaStreamWaitEvent(0, evB, 0);
    k_agg1<<<(NN + 15) / 16, 512>>>(b1);                                // #6

    // layer 2
    k_gemm2<<<(NN + 127) / 128, 256, SMEM_G2>>>(W2, att_src2, att_dst2); // #7
    k_agg2<<<(NN + 15) / 16, 512>>>(b2, out);                           // #8
}

// round 10
// speedup vs baseline: 1.1936x; 1.0412x over previous
#include <cuda_runtime.h>
#include <cuda_fp16.h>
#include <cuda_bf16.h>
#include <cstdint>

#define NN 100000
#define EE 1600000
#define TE (EE + NN)
#define NB_SCAN ((NN + 1023) / 1024)
#define SX2_STRIDE 136

// ---------------- scratch (static device globals; no allocation) -----------
__device__ __align__(16) __half g_h1[NN * 128];    // layer1 linear output (fp16)
__device__ __align__(16) float  g_out1[NN * 128];  // relu(layer1 agg out)
__device__ __align__(16) __half g_h2[NN * 32];     // layer2 linear output (fp16)
__device__ __align__(16) float g_asrc1[NN * 4];
__device__ __align__(16) float g_adst1[NN * 4];
__device__ __align__(16) float g_asrc2[NN];
__device__ __align__(16) float g_adst2[NN];
__device__ int   g_deg[NN];
__device__ int   g_rowstart[NN + 1];
__device__ int   g_cursor[NN];
__device__ int   g_csr[TE];
__device__ int   g_blockval[NB_SCAN];
__device__ int   g_blockflag[NB_SCAN];
__device__ int   g_is32;

__device__ __forceinline__ float lrelu(float x) { return x > 0.f ? x : 0.2f * x; }

// packed f32x2 helpers (for gemm2)
__device__ __forceinline__ unsigned long long pack2(float a, float b) {
    unsigned long long r;
    asm("mov.b64 %0, {%1, %2};" : "=l"(r) : "f"(a), "f"(b));
    return r;
}
__device__ __forceinline__ void unpack2(unsigned long long p, float& a, float& b) {
    asm("mov.b64 {%0, %1}, %2;" : "=f"(a), "=f"(b) : "l"(p));
}
__device__ __forceinline__ void ffma2(unsigned long long& acc, unsigned long long a,
                                      unsigned long long b) {
    asm("fma.rn.f32x2 %0, %1, %2, %0;" : "+l"(acc) : "l"(a), "l"(b));
}

__device__ __forceinline__ uint32_t smem_u32(const void* p) {
    uint32_t a;
    asm("{ .reg .u64 t; cvta.to.shared.u64 t, %1; cvt.u32.u64 %0, t; }" : "=r"(a) : "l"(p));
    return a;
}

// ldmatrix x4 (sm_75+)
__device__ __forceinline__ void ldm4(uint32_t addr, uint32_t& r0, uint32_t& r1,
                                     uint32_t& r2, uint32_t& r3) {
    asm volatile("ldmatrix.sync.aligned.m8n8.x4.shared.b16 {%0,%1,%2,%3}, [%4];"
                 : "=r"(r0), "=r"(r1), "=r"(r2), "=r"(r3) : "r"(addr));
}

// mma m16n8k16 bf16 -> f32 (sm_80+)
__device__ __forceinline__ void mma16816(float* c, uint32_t a0, uint32_t a1, uint32_t a2,
                                         uint32_t a3, uint32_t b0, uint32_t b1) {
    asm volatile(
        "mma.sync.aligned.m16n8k16.row.col.f32.bf16.bf16.f32 "
        "{%0,%1,%2,%3}, {%4,%5,%6,%7}, {%8,%9}, {%0,%1,%2,%3};"
        : "+f"(c[0]), "+f"(c[1]), "+f"(c[2]), "+f"(c[3])
        : "r"(a0), "r"(a1), "r"(a2), "r"(a3), "r"(b0), "r"(b1));
}

// ---------------- init + edge dtype detection ------------------------------
__global__ void k_init(const void* __restrict__ ei) {
    int i = blockIdx.x * blockDim.x + threadIdx.x;
    if (i < NN) { g_deg[i] = 1; g_cursor[i] = 0; }
    if (i < NB_SCAN) g_blockflag[i] = 0;
    if (i == 0) {
        const long long* p = (const long long*)ei;
        int bad = 0;
        for (int j = 0; j < 64; j++) {
            long long v = p[j];
            if (v < 0 || v >= NN) bad = 1;
        }
        g_is32 = bad;
    }
}

__device__ __forceinline__ int load_src(const void* ei, int e) {
    return g_is32 ? ((const int*)ei)[e] : (int)((const long long*)ei)[e];
}
__device__ __forceinline__ int load_dst(const void* ei, int e) {
    return g_is32 ? ((const int*)ei)[EE + e] : (int)((const long long*)ei)[EE + e];
}

// ---------------- CSR build -----------------------------------------------
__global__ void k_count(const void* __restrict__ ei) {
    int e = blockIdx.x * blockDim.x + threadIdx.x;
    if (e < EE) {
        int d = load_dst(ei, e);
        if ((unsigned)d < NN) atomicAdd(&g_deg[d], 1);
    }
}

__global__ void k_scan(void) {
    __shared__ int sh[1024];
    __shared__ int s_excl;
    int t = threadIdx.x;
    int b = blockIdx.x;
    int i = b * 1024 + t;
    int v = (i < NN) ? g_deg[i] : 0;
    sh[t] = v;
    __syncthreads();
    #pragma unroll
    for (int off = 1; off < 1024; off <<= 1) {
        int a = (t >= off) ? sh[t - off] : 0;
        __syncthreads();
        sh[t] += a;
        __syncthreads();
    }
    if (t == 1023) {
        g_blockval[b] = sh[1023];
        __threadfence();
        atomicExch(&g_blockflag[b], 1);
    }
    if (t < 32) {
        int excl = 0;
        for (int w0 = b - 1; w0 >= 0; w0 -= 32) {
            int idx = w0 - t;
            int val = 0;
            if (idx >= 0) {
                while (atomicAdd(&g_blockflag[idx], 0) == 0) {}
                __threadfence();
                val = g_blockval[idx];
            }
            #pragma unroll
            for (int off = 16; off; off >>= 1)
                val += __shfl_xor_sync(0xffffffffu, val, off);
            excl += val;
        }
        if (t == 0) s_excl = excl;
    }
    __syncthreads();
    if (i < NN) g_rowstart[i + 1] = sh[t] + s_excl;
    if (i == 0) g_rowstart[0] = 0;
}

__global__ void k_fill(const void* __restrict__ ei) {
    int t = blockIdx.x * blockDim.x + threadIdx.x;
    if (t >= TE) return;
    int s, d;
    if (t < EE) {
        s = load_src(ei, t);
        d = load_dst(ei, t);
    } else {
        s = d = t - EE;
    }
    if ((unsigned)s >= NN || (unsigned)d >= NN) return;
    int pos = g_rowstart[d] + atomicAdd(&g_cursor[d], 1);
    if ((unsigned)pos < TE) g_csr[pos] = s;
}

// ---------------- GEMM1 via mma.sync bf16 (split x3) + fused att1 ----------
// block 256 thr (8 warps), M=128 rows/block, N=128, K=128.
// warp w: rows w*16..w*16+15, all 128 cols.
// smem bytes: s_as @0 (512), s_ad @512 (512), Xhi @1024, Xlo @35840,
//             Whi @70656 (Wt [n][k]), Wlo @105472. total 140288.
#define XHI_OFF 1024
#define XLO_OFF 35840
#define WHI_OFF 70656
#define WLO_OFF 105472
#define G1_SMEM 140288
#define XSTR 136   // bf16 per row (272 B)

__global__ void __launch_bounds__(256, 1)
k_gemm1(const float* __restrict__ x, const float* __restrict__ W1,
        const float* __restrict__ att_src, const float* __restrict__ att_dst) {
    extern __shared__ char sm[];
    uint32_t smb = smem_u32(sm);
    int tid = threadIdx.x;
    int wid = tid >> 5, lane = tid & 31;
    int row0 = blockIdx.x * 128;

    float* s_as = (float*)(sm);
    float* s_ad = (float*)(sm + 512);
    if (tid < 128) {
        s_as[tid] = att_src[tid];
        s_ad[tid] = att_dst[tid];
    }

    // ---- convert x tile -> Xhi/Xlo (row-major, stride 136 bf16) ----
    {
        int r = tid >> 1;              // 0..127
        int ks = (tid & 1) * 64;       // 0 or 64
        int gr = row0 + r;
        const float4* X4 = (const float4*)x;
        char* xh = sm + XHI_OFF + r * 272 + ks * 2;
        char* xl = sm + XLO_OFF + r * 272 + ks * 2;
        #pragma unroll 4
        for (int j = 0; j < 16; j++) {
            float4 v = (gr < NN) ? X4[(size_t)gr * 32 + (ks >> 2) + j]
                                 : make_float4(0.f, 0.f, 0.f, 0.f);
            __nv_bfloat16 hx = __float2bfloat16(v.x);
            __nv_bfloat16 hy = __float2bfloat16(v.y);
            __nv_bfloat16 hz = __float2bfloat16(v.z);
            __nv_bfloat16 hw = __float2bfloat16(v.w);
            __nv_bfloat16 lx = __float2bfloat16(v.x - __bfloat162float(hx));
            __nv_bfloat16 ly = __float2bfloat16(v.y - __bfloat162float(hy));
            __nv_bfloat16 lz = __float2bfloat16(v.z - __bfloat162float(hz));
            __nv_bfloat16 lw = __float2bfloat16(v.w - __bfloat162float(hw));
            __nv_bfloat162 h01 = __halves2bfloat162(hx, hy);
            __nv_bfloat162 h23 = __halves2bfloat162(hz, hw);
            __nv_bfloat162 l01 = __halves2bfloat162(lx, ly);
            __nv_bfloat162 l23 = __halves2bfloat162(lz, lw);
            uint2 hv, lv;
            hv.x = *(uint32_t*)&h01; hv.y = *(uint32_t*)&h23;
            lv.x = *(uint32_t*)&l01; lv.y = *(uint32_t*)&l23;
            *(uint2*)(xh + j * 8) = hv;
            *(uint2*)(xl + j * 8) = lv;
        }
    }

    // ---- convert W -> Whi/Wlo transposed [n][k], stride 136 bf16 ----
    for (int idx = tid; idx < 16384; idx += 256) {
        int k = idx >> 7, n = idx & 127;
        float w = W1[idx];
        __nv_bfloat16 hi = __float2bfloat16(w);
        __nv_bfloat16 lo = __float2bfloat16(w - __bfloat162float(hi));
        *(__nv_bfloat16*)(sm + WHI_OFF + (n * XSTR + k) * 2) = hi;
        *(__nv_bfloat16*)(sm + WLO_OFF + (n * XSTR + k) * 2) = lo;
    }
    __syncthreads();

    // ---- mainloop ----
    int m0 = wid * 16;
    int q = lane >> 3, rr = lane & 7;
    // A fragment addresses (mat0: m0:8/k0:8, mat1: m8:16/k0:8, mat2: m0:8/k8, mat3: m8:16/k8)
    uint32_t aRow = (uint32_t)(m0 + rr + (q & 1) * 8);
    uint32_t aOffH = XHI_OFF + aRow * 272 + (uint32_t)(q >> 1) * 16;
    uint32_t aOffL = XLO_OFF + aRow * 272 + (uint32_t)(q >> 1) * 16;
    // B fragment addresses (mat0: n0:8/k0:8, mat1: n0:8/k8, mat2: n8:16/k0:8, mat3: n8:16/k8)
    uint32_t bRow = (uint32_t)(rr + (q >> 1) * 8);
    uint32_t bOffH = WHI_OFF + bRow * 272 + (uint32_t)(q & 1) * 16;
    uint32_t bOffL = WLO_OFF + bRow * 272 + (uint32_t)(q & 1) * 16;

    float c[16][4];
    #pragma unroll
    for (int nt = 0; nt < 16; nt++)
        #pragma unroll
        for (int e = 0; e < 4; e++) c[nt][e] = 0.f;

    #pragma unroll
    for (int kt = 0; kt < 8; kt++) {
        uint32_t ah0, ah1, ah2, ah3, al0, al1, al2, al3;
        ldm4(smb + aOffH + kt * 32, ah0, ah1, ah2, ah3);
        ldm4(smb + aOffL + kt * 32, al0, al1, al2, al3);
        #pragma unroll
        for (int np = 0; np < 8; np++) {
            uint32_t bh0, bh1, bh2, bh3, bl0, bl1, bl2, bl3;
            ldm4(smb + bOffH + np * 4352 + kt * 32, bh0, bh1, bh2, bh3);
            ldm4(smb + bOffL + np * 4352 + kt * 32, bl0, bl1, bl2, bl3);
            mma16816(c[np * 2],     ah0, ah1, ah2, ah3, bh0, bh1);
            mma16816(c[np * 2],     al0, al1, al2, al3, bh0, bh1);
            mma16816(c[np * 2],     ah0, ah1, ah2, ah3, bl0, bl1);
            mma16816(c[np * 2 + 1], ah0, ah1, ah2, ah3, bh2, bh3);
            mma16816(c[np * 2 + 1], al0, al1, al2, al3, bh2, bh3);
            mma16816(c[np * 2 + 1], ah0, ah1, ah2, ah3, bl2, bl3);
        }
    }

    // ---- epilogue: h1 (fp16) + attention coefficients ----
    int g = lane >> 2, qq = lane & 3;
    int gr0 = row0 + m0 + g;
    int gr1 = gr0 + 8;

    #pragma unroll
    for (int nt = 0; nt < 16; nt++) {
        int col = nt * 8 + qq * 2;
        if (gr0 < NN)
            *(__half2*)&g_h1[(size_t)gr0 * 128 + col] = __floats2half2_rn(c[nt][0], c[nt][1]);
        if (gr1 < NN)
            *(__half2*)&g_h1[(size_t)gr1 * 128 + col] = __floats2half2_rn(c[nt][2], c[nt][3]);
    }

    #pragma unroll
    for (int h = 0; h < 4; h++) {
        float s0 = 0.f, d0 = 0.f, s1 = 0.f, d1 = 0.f;
        #pragma unroll
        for (int t = 0; t < 4; t++) {
            int nt = h * 4 + t;
            int col = nt * 8 + qq * 2;
            float av0 = s_as[col], av1 = s_as[col + 1];
            float dv0 = s_ad[col], dv1 = s_ad[col + 1];
            s0 += c[nt][0] * av0 + c[nt][1] * av1;
            d0 += c[nt][0] * dv0 + c[nt][1] * dv1;
            s1 += c[nt][2] * av0 + c[nt][3] * av1;
            d1 += c[nt][2] * dv0 + c[nt][3] * dv1;
        }
        s0 += __shfl_xor_sync(0xffffffffu, s0, 1); s0 += __shfl_xor_sync(0xffffffffu, s0, 2);
        d0 += __shfl_xor_sync(0xffffffffu, d0, 1); d0 += __shfl_xor_sync(0xffffffffu, d0, 2);
        s1 += __shfl_xor_sync(0xffffffffu, s1, 1); s1 += __shfl_xor_sync(0xffffffffu, s1, 2);
        d1 += __shfl_xor_sync(0xffffffffu, d1, 1); d1 += __shfl_xor_sync(0xffffffffu, d1, 2);
        if (qq == 0) {
            if (gr0 < NN) { g_asrc1[gr0 * 4 + h] = s0; g_adst1[gr0 * 4 + h] = d0; }
            if (gr1 < NN) { g_asrc1[gr1 * 4 + h] = s1; g_adst1[gr1 * 4 + h] = d1; }
        }
    }
}

// ---------------- aggregation, layer 1 (scalar attention gathers) ----------
__global__ void k_agg1(const float* __restrict__ b1) {
    int warp = threadIdx.x >> 5, lane = threadIdx.x & 31;
    int n = blockIdx.x * 16 + warp;
    if (n >= NN) return;
    int base = g_rowstart[n];
    int K = g_rowstart[n + 1] - base;

    int head = lane >> 3;
    float ad_s = g_adst1[n * 4 + head];

    float den = 0.f;
    float4 acc = make_float4(0.f, 0.f, 0.f, 0.f);
    const uint2* H2 = (const uint2*)g_h1;
    const float* AS = g_asrc1;
    const int* csr = g_csr + base;

    int i = 0;
    for (; i + 3 < K; i += 4) {
        int s0 = csr[i], s1 = csr[i + 1], s2 = csr[i + 2], s3 = csr[i + 3];
        float a0 = AS[s0 * 4 + head];
        float a1 = AS[s1 * 4 + head];
        float a2 = AS[s2 * 4 + head];
        float a3 = AS[s3 * 4 + head];
        uint2 v0 = H2[(size_t)s0 * 32 + lane];
        uint2 v1 = H2[(size_t)s1 * 32 + lane];
        uint2 v2 = H2[(size_t)s2 * 32 + lane];
        uint2 v3 = H2[(size_t)s3 * 32 + lane];
        float e0 = __expf(lrelu(a0 + ad_s));
        float e1 = __expf(lrelu(a1 + ad_s));
        float e2 = __expf(lrelu(a2 + ad_s));
        float e3 = __expf(lrelu(a3 + ad_s));
        den += (e0 + e1) + (e2 + e3);
        float2 f0a = __half22float2(*(__half2*)&v0.x);
        float2 f0b = __half22float2(*(__half2*)&v0.y);
        float2 f1a = __half22float2(*(__half2*)&v1.x);
        float2 f1b = __half22float2(*(__half2*)&v1.y);
        float2 f2a = __half22float2(*(__half2*)&v2.x);
        float2 f2b = __half22float2(*(__half2*)&v2.y);
        float2 f3a = __half22float2(*(__half2*)&v3.x);
        float2 f3b = __half22float2(*(__half2*)&v3.y);
        acc.x += (e0 * f0a.x + e1 * f1a.x) + (e2 * f2a.x + e3 * f3a.x);
        acc.y += (e0 * f0a.y + e1 * f1a.y) + (e2 * f2a.y + e3 * f3a.y);
        acc.z += (e0 * f0b.x + e1 * f1b.x) + (e2 * f2b.x + e3 * f3b.x);
        acc.w += (e0 * f0b.y + e1 * f1b.y) + (e2 * f2b.y + e3 * f3b.y);
    }
    for (; i < K; i++) {
        int s0 = csr[i];
        float a0 = AS[s0 * 4 + head];
        uint2 v0 = H2[(size_t)s0 * 32 + lane];
        float e0 = __expf(lrelu(a0 + ad_s));
        den += e0;
        float2 f0a = __half22float2(*(__half2*)&v0.x);
        float2 f0b = __half22float2(*(__half2*)&v0.y);
        acc.x += e0 * f0a.x;
        acc.y += e0 * f0a.y;
        acc.z += e0 * f0b.x;
        acc.w += e0 * f0b.y;
    }

    float inv = 1.f / (den + 1e-16f);
    float4 b = ((const float4*)b1)[lane];
    float4 o;
    o.x = fmaxf(acc.x * inv + b.x, 0.f);
    o.y = fmaxf(acc.y * inv + b.y, 0.f);
    o.z = fmaxf(acc.z * inv + b.z, 0.f);
    o.w = fmaxf(acc.w * inv + b.w, 0.f);
    ((float4*)g_out1)[(size_t)n * 32 + lane] = o;
}

// ---------------- GEMM2: h2 = out1 @ W2 (128x32) + fused attention coeffs --
__global__ void k_gemm2(const float* __restrict__ W2,
                        const float* __restrict__ att_src, const float* __restrict__ att_dst) {
    extern __shared__ float smf[];
    float* sW = smf;
    float* sX = smf + 128 * 32;
    int tid = threadIdx.x;
    int row0 = blockIdx.x * 128;

    float4* sW4 = (float4*)sW;
    const float4* W4 = (const float4*)W2;
    for (int j = tid; j < 1024; j += 256) sW4[j] = W4[j];

    const float4* X4 = (const float4*)g_out1;
    for (int j = tid; j < 4096; j += 256) {
        int r = j >> 5, c = j & 31;
        int gr = row0 + r;
        float4 v = (gr < NN) ? X4[(size_t)gr * 32 + c] : make_float4(0.f, 0.f, 0.f, 0.f);
        *(float4*)&sX[r * SX2_STRIDE + c * 4] = v;
    }
    __syncthreads();

    int tc = tid & 7;
    int tr = tid >> 3;
    unsigned long long accp[4][2];
    #pragma unroll
    for (int m = 0; m < 4; m++) { accp[m][0] = 0ull; accp[m][1] = 0ull; }

    for (int k4 = 0; k4 < 32; k4++) {
        float4 xq[4];
        #pragma unroll
        for (int m = 0; m < 4; m++)
            xq[m] = *(const float4*)&sX[(tr + 32 * m) * SX2_STRIDE + k4 * 4];
        #pragma unroll
        for (int kk = 0; kk < 4; kk++) {
            float4 w = sW4[(k4 * 4 + kk) * 8 + tc];
            unsigned long long wlo = pack2(w.x, w.y);
            unsigned long long whi = pack2(w.z, w.w);
            #pragma unroll
            for (int m = 0; m < 4; m++) {
                float xv = (kk == 0) ? xq[m].x : (kk == 1) ? xq[m].y
                          : (kk == 2) ? xq[m].z : xq[m].w;
                unsigned long long xp = pack2(xv, xv);
                ffma2(accp[m][0], xp, wlo);
                ffma2(accp[m][1], xp, whi);
            }
        }
    }

    float4 av_s = ((const float4*)att_src)[tc];
    float4 av_d = ((const float4*)att_dst)[tc];

    uint2* H2 = (uint2*)g_h2;
    #pragma unroll
    for (int m = 0; m < 4; m++) {
        float4 h;
        unpack2(accp[m][0], h.x, h.y);
        unpack2(accp[m][1], h.z, h.w);
        int gr = row0 + tr + 32 * m;
        if (gr < NN) {
            __half2 p01 = __floats2half2_rn(h.x, h.y);
            __half2 p23 = __floats2half2_rn(h.z, h.w);
            uint2 v;
            v.x = *(unsigned*)&p01;
            v.y = *(unsigned*)&p23;
            H2[(size_t)gr * 8 + tc] = v;
        }

        float s = h.x * av_s.x + h.y * av_s.y + h.z * av_s.z + h.w * av_s.w;
        float d = h.x * av_d.x + h.y * av_d.y + h.z * av_d.z + h.w * av_d.w;
        #pragma unroll
        for (int off = 4; off; off >>= 1) {
            s += __shfl_xor_sync(0xffffffffu, s, off);
            d += __shfl_xor_sync(0xffffffffu, d, off);
        }
        if (tc == 0 && gr < NN) {
            g_asrc2[gr] = s;
            g_adst2[gr] = d;
        }
    }
}

// ---------------- aggregation, layer 2 ------------------------------------
__global__ void k_agg2(const float* __restrict__ b2, float* __restrict__ out) {
    int warp = threadIdx.x >> 5, lane = threadIdx.x & 31;
    int n = blockIdx.x * 16 + warp;
    if (n >= NN) return;
    int base = g_rowstart[n];
    int K = g_rowstart[n + 1] - base;
    float ad = g_adst2[n];
    const int* csr = g_csr + base;

    float den = 0.f, acc = 0.f;
    int i = 0;
    for (; i + 3 < K; i += 4) {
        int s0 = csr[i], s1 = csr[i + 1], s2 = csr[i + 2], s3 = csr[i + 3];
        float a0 = g_asrc2[s0];
        float a1 = g_asrc2[s1];
        float a2 = g_asrc2[s2];
        float a3 = g_asrc2[s3];
        float h0 = __half2float(g_h2[(size_t)s0 * 32 + lane]);
        float h1 = __half2float(g_h2[(size_t)s1 * 32 + lane]);
        float h2 = __half2float(g_h2[(size_t)s2 * 32 + lane]);
        float h3 = __half2float(g_h2[(size_t)s3 * 32 + lane]);
        float e0 = __expf(lrelu(a0 + ad));
        float e1 = __expf(lrelu(a1 + ad));
        float e2 = __expf(lrelu(a2 + ad));
        float e3 = __expf(lrelu(a3 + ad));
        den += (e0 + e1) + (e2 + e3);
        acc += (e0 * h0 + e1 * h1) + (e2 * h2 + e3 * h3);
    }
    for (; i < K; i++) {
        int s0 = csr[i];
        float e0 = __expf(lrelu(g_asrc2[s0] + ad));
        den += e0;
        acc += e0 * __half2float(g_h2[(size_t)s0 * 32 + lane]);
    }
    out[(size_t)n * 32 + lane] = acc / (den + 1e-16f) + b2[lane];
}

// ---------------- launch ---------------------------------------------------
extern "C" void kernel_launch(void* const* d_in, const int* in_sizes, int n_in,
                              void* d_out, int out_size) {
    const float* x        = (const float*)d_in[0];
    const void*  ei       = d_in[1];
    const float* W1       = (const float*)d_in[2];
    const float* att_src1 = (const float*)d_in[3];
    const float* att_dst1 = (const float*)d_in[4];
    const float* b1       = (const float*)d_in[5];
    const float* W2       = (const float*)d_in[6];
    const float* att_src2 = (const float*)d_in[7];
    const float* att_dst2 = (const float*)d_in[8];
    const float* b2       = (const float*)d_in[9];
    float*       out      = (float*)d_out;

    const int SMEM_G2 = (128 * 32 + 128 * SX2_STRIDE) * 4;
    cudaFuncSetAttribute(k_gemm1, cudaFuncAttributeMaxDynamicSharedMemorySize, G1_SMEM);
    cudaFuncSetAttribute(k_gemm2, cudaFuncAttributeMaxDynamicSharedMemorySize, SMEM_G2);

    cudaStream_t s1;
    cudaStreamCreateWithFlags(&s1, cudaStreamNonBlocking);
    cudaEvent_t evA, evB;
    cudaEventCreateWithFlags(&evA, cudaEventDisableTiming);
    cudaEventCreateWithFlags(&evB, cudaEventDisableTiming);

    k_init<<<(NN + 255) / 256, 256>>>(ei);                                  // #1
    cudaEventRecord(evA, 0);
    cudaStreamWaitEvent(s1, evA, 0);

    k_count<<<(EE + 255) / 256, 256, 0, s1>>>(ei);                          // #2
    k_scan<<<NB_SCAN, 1024, 0, s1>>>();                                     // #3

    // main stream: HMMA GEMM1 (ncu target = launch #4)
    k_gemm1<<<(NN + 127) / 128, 256, G1_SMEM>>>(x, W1, att_src1, att_dst1); // #4

    k_fill<<<(TE + 255) / 256, 256, 0, s1>>>(ei);                           // #5
    cudaEventRecord(evB, s1);

    cudaStreamWaitEvent(0, evB, 0);
    k_agg1<<<(NN + 15) / 16, 512>>>(b1);                                    // #6

    k_gemm2<<<(NN + 127) / 128, 256, SMEM_G2>>>(W2, att_src2, att_dst2);    // #7
    k_agg2<<<(NN + 15) / 16, 512>>>(b2, out);                               // #8
}

// round 11
// speedup vs baseline: 1.2624x; 1.0576x over previous
#include <cuda_runtime.h>
#include <cuda_fp16.h>
#include <cuda_bf16.h>
#include <cstdint>

#define NN 100000
#define EE 1600000
#define TE (EE + NN)
#define NB_SCAN ((NN + 1023) / 1024)
#define SX2_STRIDE 136

// ---------------- scratch (static device globals; no allocation) -----------
__device__ __align__(16) __half g_h1[NN * 128];    // layer1 linear output (fp16)
__device__ __align__(16) float  g_out1[NN * 128];  // relu(layer1 agg out)
__device__ __align__(16) __half g_h2[NN * 32];     // layer2 linear output (fp16)
__device__ __align__(16) float g_asrc1[NN * 4];
__device__ __align__(16) float g_adst1[NN * 4];
__device__ __align__(16) float g_asrc2[NN];
__device__ __align__(16) float g_adst2[NN];
__device__ __align__(16) unsigned short g_w1hi[128 * 136];  // bf16, padded [n][k]
__device__ __align__(16) unsigned short g_w1lo[128 * 136];
__device__ int   g_deg[NN];
__device__ int   g_rowstart[NN + 1];
__device__ int   g_cursor[NN];
__device__ int   g_csr[TE];
__device__ int   g_blockval[NB_SCAN];
__device__ int   g_blockflag[NB_SCAN];
__device__ int   g_is32;

__device__ __forceinline__ float lrelu(float x) { return x > 0.f ? x : 0.2f * x; }

// packed f32x2 helpers (for gemm2)
__device__ __forceinline__ unsigned long long pack2(float a, float b) {
    unsigned long long r;
    asm("mov.b64 %0, {%1, %2};" : "=l"(r) : "f"(a), "f"(b));
    return r;
}
__device__ __forceinline__ void unpack2(unsigned long long p, float& a, float& b) {
    asm("mov.b64 {%0, %1}, %2;" : "=f"(a), "=f"(b) : "l"(p));
}
__device__ __forceinline__ void ffma2(unsigned long long& acc, unsigned long long a,
                                      unsigned long long b) {
    asm("fma.rn.f32x2 %0, %1, %2, %0;" : "+l"(acc) : "l"(a), "l"(b));
}

__device__ __forceinline__ uint32_t smem_u32(const void* p) {
    uint32_t a;
    asm("{ .reg .u64 t; cvta.to.shared.u64 t, %1; cvt.u32.u64 %0, t; }" : "=r"(a) : "l"(p));
    return a;
}

__device__ __forceinline__ void ldm4(uint32_t addr, uint32_t& r0, uint32_t& r1,
                                     uint32_t& r2, uint32_t& r3) {
    asm volatile("ldmatrix.sync.aligned.m8n8.x4.shared.b16 {%0,%1,%2,%3}, [%4];"
                 : "=r"(r0), "=r"(r1), "=r"(r2), "=r"(r3) : "r"(addr));
}

__device__ __forceinline__ void mma16816(float* c, uint32_t a0, uint32_t a1, uint32_t a2,
                                         uint32_t a3, uint32_t b0, uint32_t b1) {
    asm volatile(
        "mma.sync.aligned.m16n8k16.row.col.f32.bf16.bf16.f32 "
        "{%0,%1,%2,%3}, {%4,%5,%6,%7}, {%8,%9}, {%0,%1,%2,%3};"
        : "+f"(c[0]), "+f"(c[1]), "+f"(c[2]), "+f"(c[3])
        : "r"(a0), "r"(a1), "r"(a2), "r"(a3), "r"(b0), "r"(b1));
}

// ---------------- init + dtype detect + W1 bf16-split precompute -----------
__global__ void k_init(const void* __restrict__ ei, const float* __restrict__ W1) {
    int i = blockIdx.x * blockDim.x + threadIdx.x;
    if (i < NN) { g_deg[i] = 1; g_cursor[i] = 0; }
    if (i < NB_SCAN) g_blockflag[i] = 0;
    if (i < 16384) {
        int k = i >> 7, n = i & 127;
        float w = W1[i];
        __nv_bfloat16 hi = __float2bfloat16(w);
        __nv_bfloat16 lo = __float2bfloat16(w - __bfloat162float(hi));
        g_w1hi[n * 136 + k] = *(unsigned short*)&hi;
        g_w1lo[n * 136 + k] = *(unsigned short*)&lo;
    }
    if (i == 0) {
        const long long* p = (const long long*)ei;
        int bad = 0;
        for (int j = 0; j < 64; j++) {
            long long v = p[j];
            if (v < 0 || v >= NN) bad = 1;
        }
        g_is32 = bad;
    }
}

__device__ __forceinline__ int load_src(const void* ei, int e) {
    return g_is32 ? ((const int*)ei)[e] : (int)((const long long*)ei)[e];
}
__device__ __forceinline__ int load_dst(const void* ei, int e) {
    return g_is32 ? ((const int*)ei)[EE + e] : (int)((const long long*)ei)[EE + e];
}

// ---------------- CSR build -----------------------------------------------
__global__ void k_count(const void* __restrict__ ei) {
    int e = blockIdx.x * blockDim.x + threadIdx.x;
    if (e < EE) {
        int d = load_dst(ei, e);
        if ((unsigned)d < NN) atomicAdd(&g_deg[d], 1);
    }
}

__global__ void k_scan(void) {
    __shared__ int sh[1024];
    __shared__ int s_excl;
    int t = threadIdx.x;
    int b = blockIdx.x;
    int i = b * 1024 + t;
    int v = (i < NN) ? g_deg[i] : 0;
    sh[t] = v;
    __syncthreads();
    #pragma unroll
    for (int off = 1; off < 1024; off <<= 1) {
        int a = (t >= off) ? sh[t - off] : 0;
        __syncthreads();
        sh[t] += a;
        __syncthreads();
    }
    if (t == 1023) {
        g_blockval[b] = sh[1023];
        __threadfence();
        atomicExch(&g_blockflag[b], 1);
    }
    if (t < 32) {
        int excl = 0;
        for (int w0 = b - 1; w0 >= 0; w0 -= 32) {
            int idx = w0 - t;
            int val = 0;
            if (idx >= 0) {
                while (atomicAdd(&g_blockflag[idx], 0) == 0) {}
                __threadfence();
                val = g_blockval[idx];
            }
            #pragma unroll
            for (int off = 16; off; off >>= 1)
                val += __shfl_xor_sync(0xffffffffu, val, off);
            excl += val;
        }
        if (t == 0) s_excl = excl;
    }
    __syncthreads();
    if (i < NN) g_rowstart[i + 1] = sh[t] + s_excl;
    if (i == 0) g_rowstart[0] = 0;
}

__global__ void k_fill(const void* __restrict__ ei) {
    int t = blockIdx.x * blockDim.x + threadIdx.x;
    if (t >= TE) return;
    int s, d;
    if (t < EE) {
        s = load_src(ei, t);
        d = load_dst(ei, t);
    } else {
        s = d = t - EE;
    }
    if ((unsigned)s >= NN || (unsigned)d >= NN) return;
    int pos = g_rowstart[d] + atomicAdd(&g_cursor[d], 1);
    if ((unsigned)pos < TE) g_csr[pos] = s;
}

// ---------------- GEMM1 via mma.sync bf16 (split x3) + fused att1 ----------
// block 256 thr (8 warps), M=64 rows/block, N=128, K=128.
// warp w: rows (w>>1)*16..+15, cols (w&1)*64..+63 (covers 2 heads fully).
// smem bytes: s_as @0 (512), s_ad @512 (512), Xhi @1024 (64*272=17408),
//             Xlo @18432, Whi @35840 (34816), Wlo @70656. total 105472.
#define XHI_OFF 1024
#define XLO_OFF 18432
#define WHI_OFF 35840
#define WLO_OFF 70656
#define G1_SMEM 105472

__global__ void __launch_bounds__(256, 2)
k_gemm1(const float* __restrict__ x,
        const float* __restrict__ att_src, const float* __restrict__ att_dst) {
    extern __shared__ char sm[];
    uint32_t smb = smem_u32(sm);
    int tid = threadIdx.x;
    int wid = tid >> 5, lane = tid & 31;
    int row0 = blockIdx.x * 64;

    float* s_as = (float*)(sm);
    float* s_ad = (float*)(sm + 512);
    if (tid < 128) {
        s_as[tid] = att_src[tid];
        s_ad[tid] = att_dst[tid];
    }

    // ---- copy W hi/lo tiles (already padded bf16 in global) ----
    {
        const uint4* WH4 = (const uint4*)g_w1hi;
        const uint4* WL4 = (const uint4*)g_w1lo;
        uint4* sWH = (uint4*)(sm + WHI_OFF);
        uint4* sWL = (uint4*)(sm + WLO_OFF);
        #pragma unroll
        for (int j = tid; j < 2176; j += 256) {
            sWH[j] = WH4[j];
            sWL[j] = WL4[j];
        }
    }

    // ---- convert x tile (64 rows) -> Xhi/Xlo ----
    {
        int r = tid >> 2;              // 0..63
        int ks = (tid & 3) * 32;       // col start (floats)
        int gr = row0 + r;
        const float4* X4 = (const float4*)x;
        char* xh = sm + XHI_OFF + r * 272 + ks * 2;
        char* xl = sm + XLO_OFF + r * 272 + ks * 2;
        #pragma unroll
        for (int j = 0; j < 8; j++) {
            float4 v = (gr < NN) ? X4[(size_t)gr * 32 + (ks >> 2) + j]
                                 : make_float4(0.f, 0.f, 0.f, 0.f);
            __nv_bfloat16 hx = __float2bfloat16(v.x);
            __nv_bfloat16 hy = __float2bfloat16(v.y);
            __nv_bfloat16 hz = __float2bfloat16(v.z);
            __nv_bfloat16 hw = __float2bfloat16(v.w);
            __nv_bfloat16 lx = __float2bfloat16(v.x - __bfloat162float(hx));
            __nv_bfloat16 ly = __float2bfloat16(v.y - __bfloat162float(hy));
            __nv_bfloat16 lz = __float2bfloat16(v.z - __bfloat162float(hz));
            __nv_bfloat16 lw = __float2bfloat16(v.w - __bfloat162float(hw));
            __nv_bfloat162 h01 = __halves2bfloat162(hx, hy);
            __nv_bfloat162 h23 = __halves2bfloat162(hz, hw);
            __nv_bfloat162 l01 = __halves2bfloat162(lx, ly);
            __nv_bfloat162 l23 = __halves2bfloat162(lz, lw);
            uint2 hv, lv;
            hv.x = *(uint32_t*)&h01; hv.y = *(uint32_t*)&h23;
            lv.x = *(uint32_t*)&l01; lv.y = *(uint32_t*)&l23;
            *(uint2*)(xh + j * 8) = hv;
            *(uint2*)(xl + j * 8) = lv;
        }
    }
    __syncthreads();

    // ---- mainloop: warp tile 16 rows x 64 cols ----
    int m0 = (wid >> 1) * 16;
    int ch = (wid & 1) * 64;           // col half
    int q = lane >> 3, rr = lane & 7;
    uint32_t aRow = (uint32_t)(m0 + rr + (q & 1) * 8);
    uint32_t aOffH = XHI_OFF + aRow * 272 + (uint32_t)(q >> 1) * 16;
    uint32_t aOffL = XLO_OFF + aRow * 272 + (uint32_t)(q >> 1) * 16;
    uint32_t bRow = (uint32_t)(ch + rr + (q >> 1) * 8);
    uint32_t bOffH = WHI_OFF + bRow * 272 + (uint32_t)(q & 1) * 16;
    uint32_t bOffL = WLO_OFF + bRow * 272 + (uint32_t)(q & 1) * 16;

    float c[8][4];
    #pragma unroll
    for (int nt = 0; nt < 8; nt++)
        #pragma unroll
        for (int e = 0; e < 4; e++) c[nt][e] = 0.f;

    #pragma unroll
    for (int kt = 0; kt < 8; kt++) {
        uint32_t ah0, ah1, ah2, ah3, al0, al1, al2, al3;
        ldm4(smb + aOffH + kt * 32, ah0, ah1, ah2, ah3);
        ldm4(smb + aOffL + kt * 32, al0, al1, al2, al3);
        #pragma unroll
        for (int np = 0; np < 4; np++) {
            uint32_t bh0, bh1, bh2, bh3, bl0, bl1, bl2, bl3;
            ldm4(smb + bOffH + np * 4352 + kt * 32, bh0, bh1, bh2, bh3);
            ldm4(smb + bOffL + np * 4352 + kt * 32, bl0, bl1, bl2, bl3);
            mma16816(c[np * 2],     ah0, ah1, ah2, ah3, bh0, bh1);
            mma16816(c[np * 2],     al0, al1, al2, al3, bh0, bh1);
            mma16816(c[np * 2],     ah0, ah1, ah2, ah3, bl0, bl1);
            mma16816(c[np * 2 + 1], ah0, ah1, ah2, ah3, bh2, bh3);
            mma16816(c[np * 2 + 1], al0, al1, al2, al3, bh2, bh3);
            mma16816(c[np * 2 + 1], ah0, ah1, ah2, ah3, bl2, bl3);
        }
    }

    // ---- epilogue: h1 (fp16) + attention coefficients (2 heads/warp) ----
    int g = lane >> 2, qq = lane & 3;
    int gr0 = row0 + m0 + g;
    int gr1 = gr0 + 8;

    #pragma unroll
    for (int nt = 0; nt < 8; nt++) {
        int col = ch + nt * 8 + qq * 2;
        if (gr0 < NN)
            *(__half2*)&g_h1[(size_t)gr0 * 128 + col] = __floats2half2_rn(c[nt][0], c[nt][1]);
        if (gr1 < NN)
            *(__half2*)&g_h1[(size_t)gr1 * 128 + col] = __floats2half2_rn(c[nt][2], c[nt][3]);
    }

    #pragma unroll
    for (int hl = 0; hl < 2; hl++) {          // local head -> global head
        int gh = (ch >> 5) + hl;
        float s0 = 0.f, d0 = 0.f, s1 = 0.f, d1 = 0.f;
        #pragma unroll
        for (int t = 0; t < 4; t++) {
            int nt = hl * 4 + t;
            int col = ch + nt * 8 + qq * 2;
            float av0 = s_as[col], av1 = s_as[col + 1];
            float dv0 = s_ad[col], dv1 = s_ad[col + 1];
            s0 += c[nt][0] * av0 + c[nt][1] * av1;
            d0 += c[nt][0] * dv0 + c[nt][1] * dv1;
            s1 += c[nt][2] * av0 + c[nt][3] * av1;
            d1 += c[nt][2] * dv0 + c[nt][3] * dv1;
        }
        s0 += __shfl_xor_sync(0xffffffffu, s0, 1); s0 += __shfl_xor_sync(0xffffffffu, s0, 2);
        d0 += __shfl_xor_sync(0xffffffffu, d0, 1); d0 += __shfl_xor_sync(0xffffffffu, d0, 2);
        s1 += __shfl_xor_sync(0xffffffffu, s1, 1); s1 += __shfl_xor_sync(0xffffffffu, s1, 2);
        d1 += __shfl_xor_sync(0xffffffffu, d1, 1); d1 += __shfl_xor_sync(0xffffffffu, d1, 2);
        if (qq == 0) {
            if (gr0 < NN) { g_asrc1[gr0 * 4 + gh] = s0; g_adst1[gr0 * 4 + gh] = d0; }
            if (gr1 < NN) { g_asrc1[gr1 * 4 + gh] = s1; g_adst1[gr1 * 4 + gh] = d1; }
        }
    }
}

// ---------------- aggregation, layer 1 (scalar attention gathers) ----------
__global__ void k_agg1(const float* __restrict__ b1) {
    int warp = threadIdx.x >> 5, lane = threadIdx.x & 31;
    int n = blockIdx.x * 16 + warp;
    if (n >= NN) return;
    int base = g_rowstart[n];
    int K = g_rowstart[n + 1] - base;

    int head = lane >> 3;
    float ad_s = g_adst1[n * 4 + head];

    float den = 0.f;
    float4 acc = make_float4(0.f, 0.f, 0.f, 0.f);
    const uint2* H2 = (const uint2*)g_h1;
    const float* AS = g_asrc1;
    const int* csr = g_csr + base;

    int i = 0;
    for (; i + 3 < K; i += 4) {
        int s0 = csr[i], s1 = csr[i + 1], s2 = csr[i + 2], s3 = csr[i + 3];
        float a0 = AS[s0 * 4 + head];
        float a1 = AS[s1 * 4 + head];
        float a2 = AS[s2 * 4 + head];
        float a3 = AS[s3 * 4 + head];
        uint2 v0 = H2[(size_t)s0 * 32 + lane];
        uint2 v1 = H2[(size_t)s1 * 32 + lane];
        uint2 v2 = H2[(size_t)s2 * 32 + lane];
        uint2 v3 = H2[(size_t)s3 * 32 + lane];
        float e0 = __expf(lrelu(a0 + ad_s));
        float e1 = __expf(lrelu(a1 + ad_s));
        float e2 = __expf(lrelu(a2 + ad_s));
        float e3 = __expf(lrelu(a3 + ad_s));
        den += (e0 + e1) + (e2 + e3);
        float2 f0a = __half22float2(*(__half2*)&v0.x);
        float2 f0b = __half22float2(*(__half2*)&v0.y);
        float2 f1a = __half22float2(*(__half2*)&v1.x);
        float2 f1b = __half22float2(*(__half2*)&v1.y);
        float2 f2a = __half22float2(*(__half2*)&v2.x);
        float2 f2b = __half22float2(*(__half2*)&v2.y);
        float2 f3a = __half22float2(*(__half2*)&v3.x);
        float2 f3b = __half22float2(*(__half2*)&v3.y);
        acc.x += (e0 * f0a.x + e1 * f1a.x) + (e2 * f2a.x + e3 * f3a.x);
        acc.y += (e0 * f0a.y + e1 * f1a.y) + (e2 * f2a.y + e3 * f3a.y);
        acc.z += (e0 * f0b.x + e1 * f1b.x) + (e2 * f2b.x + e3 * f3b.x);
        acc.w += (e0 * f0b.y + e1 * f1b.y) + (e2 * f2b.y + e3 * f3b.y);
    }
    for (; i < K; i++) {
        int s0 = csr[i];
        float a0 = AS[s0 * 4 + head];
        uint2 v0 = H2[(size_t)s0 * 32 + lane];
        float e0 = __expf(lrelu(a0 + ad_s));
        den += e0;
        float2 f0a = __half22float2(*(__half2*)&v0.x);
        float2 f0b = __half22float2(*(__half2*)&v0.y);
        acc.x += e0 * f0a.x;
        acc.y += e0 * f0a.y;
        acc.z += e0 * f0b.x;
        acc.w += e0 * f0b.y;
    }

    float inv = 1.f / (den + 1e-16f);
    float4 b = ((const float4*)b1)[lane];
    float4 o;
    o.x = fmaxf(acc.x * inv + b.x, 0.f);
    o.y = fmaxf(acc.y * inv + b.y, 0.f);
    o.z = fmaxf(acc.z * inv + b.z, 0.f);
    o.w = fmaxf(acc.w * inv + b.w, 0.f);
    ((float4*)g_out1)[(size_t)n * 32 + lane] = o;
}

// ---------------- GEMM2: h2 = out1 @ W2 (128x32) + fused attention coeffs --
__global__ void k_gemm2(const float* __restrict__ W2,
                        const float* __restrict__ att_src, const float* __restrict__ att_dst) {
    extern __shared__ float smf[];
    float* sW = smf;
    float* sX = smf + 128 * 32;
    int tid = threadIdx.x;
    int row0 = blockIdx.x * 128;

    float4* sW4 = (float4*)sW;
    const float4* W4 = (const float4*)W2;
    for (int j = tid; j < 1024; j += 256) sW4[j] = W4[j];

    const float4* X4 = (const float4*)g_out1;
    for (int j = tid; j < 4096; j += 256) {
        int r = j >> 5, c = j & 31;
        int gr = row0 + r;
        float4 v = (gr < NN) ? X4[(size_t)gr * 32 + c] : make_float4(0.f, 0.f, 0.f, 0.f);
        *(float4*)&sX[r * SX2_STRIDE + c * 4] = v;
    }
    __syncthreads();

    int tc = tid & 7;
    int tr = tid >> 3;
    unsigned long long accp[4][2];
    #pragma unroll
    for (int m = 0; m < 4; m++) { accp[m][0] = 0ull; accp[m][1] = 0ull; }

    for (int k4 = 0; k4 < 32; k4++) {
        float4 xq[4];
        #pragma unroll
        for (int m = 0; m < 4; m++)
            xq[m] = *(const float4*)&sX[(tr + 32 * m) * SX2_STRIDE + k4 * 4];
        #pragma unroll
        for (int kk = 0; kk < 4; kk++) {
            float4 w = sW4[(k4 * 4 + kk) * 8 + tc];
            unsigned long long wlo = pack2(w.x, w.y);
            unsigned long long whi = pack2(w.z, w.w);
            #pragma unroll
            for (int m = 0; m < 4; m++) {
                float xv = (kk == 0) ? xq[m].x : (kk == 1) ? xq[m].y
                          : (kk == 2) ? xq[m].z : xq[m].w;
                unsigned long long xp = pack2(xv, xv);
                ffma2(accp[m][0], xp, wlo);
                ffma2(accp[m][1], xp, whi);
            }
        }
    }

    float4 av_s = ((const float4*)att_src)[tc];
    float4 av_d = ((const float4*)att_dst)[tc];

    uint2* H2 = (uint2*)g_h2;
    #pragma unroll
    for (int m = 0; m < 4; m++) {
        float4 h;
        unpack2(accp[m][0], h.x, h.y);
        unpack2(accp[m][1], h.z, h.w);
        int gr = row0 + tr + 32 * m;
        if (gr < NN) {
            __half2 p01 = __floats2half2_rn(h.x, h.y);
            __half2 p23 = __floats2half2_rn(h.z, h.w);
            uint2 v;
            v.x = *(unsigned*)&p01;
            v.y = *(unsigned*)&p23;
            H2[(size_t)gr * 8 + tc] = v;
        }

        float s = h.x * av_s.x + h.y * av_s.y + h.z * av_s.z + h.w * av_s.w;
        float d = h.x * av_d.x + h.y * av_d.y + h.z * av_d.z + h.w * av_d.w;
        #pragma unroll
        for (int off = 4; off; off >>= 1) {
            s += __shfl_xor_sync(0xffffffffu, s, off);
            d += __shfl_xor_sync(0xffffffffu, d, off);
        }
        if (tc == 0 && gr < NN) {
            g_asrc2[gr] = s;
            g_adst2[gr] = d;
        }
    }
}

// ---------------- aggregation, layer 2 ------------------------------------
__global__ void k_agg2(const float* __restrict__ b2, float* __restrict__ out) {
    int warp = threadIdx.x >> 5, lane = threadIdx.x & 31;
    int n = blockIdx.x * 16 + warp;
    if (n >= NN) return;
    int base = g_rowstart[n];
    int K = g_rowstart[n + 1] - base;
    float ad = g_adst2[n];
    const int* csr = g_csr + base;

    float den = 0.f, acc = 0.f;
    int i = 0;
    for (; i + 3 < K; i += 4) {
        int s0 = csr[i], s1 = csr[i + 1], s2 = csr[i + 2], s3 = csr[i + 3];
        float a0 = g_asrc2[s0];
        float a1 = g_asrc2[s1];
        float a2 = g_asrc2[s2];
        float a3 = g_asrc2[s3];
        float h0 = __half2float(g_h2[(size_t)s0 * 32 + lane]);
        float h1 = __half2float(g_h2[(size_t)s1 * 32 + lane]);
        float h2 = __half2float(g_h2[(size_t)s2 * 32 + lane]);
        float h3 = __half2float(g_h2[(size_t)s3 * 32 + lane]);
        float e0 = __expf(lrelu(a0 + ad));
        float e1 = __expf(lrelu(a1 + ad));
        float e2 = __expf(lrelu(a2 + ad));
        float e3 = __expf(lrelu(a3 + ad));
        den += (e0 + e1) + (e2 + e3);
        acc += (e0 * h0 + e1 * h1) + (e2 * h2 + e3 * h3);
    }
    for (; i < K; i++) {
        int s0 = csr[i];
        float e0 = __expf(lrelu(g_asrc2[s0] + ad));
        den += e0;
        acc += e0 * __half2float(g_h2[(size_t)s0 * 32 + lane]);
    }
    out[(size_t)n * 32 + lane] = acc / (den + 1e-16f) + b2[lane];
}

// ---------------- launch ---------------------------------------------------
extern "C" void kernel_launch(void* const* d_in, const int* in_sizes, int n_in,
                              void* d_out, int out_size) {
    const float* x        = (const float*)d_in[0];
    const void*  ei       = d_in[1];
    const float* W1       = (const float*)d_in[2];
    const float* att_src1 = (const float*)d_in[3];
    const float* att_dst1 = (const float*)d_in[4];
    const float* b1       = (const float*)d_in[5];
    const float* W2       = (const float*)d_in[6];
    const float* att_src2 = (const float*)d_in[7];
    const float* att_dst2 = (const float*)d_in[8];
    const float* b2       = (const float*)d_in[9];
    float*       out      = (float*)d_out;

    const int SMEM_G2 = (128 * 32 + 128 * SX2_STRIDE) * 4;
    cudaFuncSetAttribute(k_gemm1, cudaFuncAttributeMaxDynamicSharedMemorySize, G1_SMEM);
    cudaFuncSetAttribute(k_gemm2, cudaFuncAttributeMaxDynamicSharedMemorySize, SMEM_G2);

    cudaStream_t s1;
    cudaStreamCreateWithFlags(&s1, cudaStreamNonBlocking);
    cudaEvent_t evA, evB;
    cudaEventCreateWithFlags(&evA, cudaEventDisableTiming);
    cudaEventCreateWithFlags(&evB, cudaEventDisableTiming);

    k_init<<<(NN + 255) / 256, 256>>>(ei, W1);                              // #1
    cudaEventRecord(evA, 0);
    cudaStreamWaitEvent(s1, evA, 0);

    k_count<<<(EE + 255) / 256, 256, 0, s1>>>(ei);                          // #2
    k_scan<<<NB_SCAN, 1024, 0, s1>>>();                                     // #3

    // main stream: HMMA GEMM1 (ncu target = launch #4)
    k_gemm1<<<(NN + 63) / 64, 256, G1_SMEM>>>(x, att_src1, att_dst1);       // #4

    k_fill<<<(TE + 255) / 256, 256, 0, s1>>>(ei);                           // #5
    cudaEventRecord(evB, s1);

    cudaStreamWaitEvent(0, evB, 0);
    k_agg1<<<(NN + 15) / 16, 512>>>(b1);                                    // #6

    k_gemm2<<<(NN + 127) / 128, 256, SMEM_G2>>>(W2, att_src2, att_dst2);    // #7
    k_agg2<<<(NN + 15) / 16, 512>>>(b2, out);                               // #8
}